// round 10
// baseline (speedup 1.0000x reference)
#include <cuda_runtime.h>
#include <math.h>

// Bit-exact replication of the JAX reference on XLA:CPU (validated R9, rel_err=0.0):
//   - outside fori_loop: all plain __f*_rn ops in reference association order
//   - inside fori_loop body: FMA-contracted F/Fp (separate XLA computation)
//   - exp = fused-Cephes GenerateVF32Exp
// R10 perf change (FP stream untouched): Newton runs TWO exact steps per trip;
// since g is deterministic, Te_{k+2}==Te_k implies period<=2, so converged
// lanes freeze under Te=T2 with no select logic, and (50 even) the frozen value
// is exactly the reference's iteration-50 value. Warp-uniform __all_sync exit
// replaces the divergent break (same executed iterations: warp waits for its
// slowest lane either way; removes BSSY/BSYNC + per-lane branch overhead).
// Lanes that never close run all 25 trips = exactly 50 exact iterations.

__device__ __forceinline__ float xla_vf32_exp(float x)
{
    x = fminf(x, 88.3762626647950f);
    x = fmaxf(x, -88.3762626647949f);

    float fx = floorf(fmaf(x, 1.44269504088896341f, 0.5f));

    float tmp = __fmul_rn(fx, 0.693359375f);
    float z   = __fmul_rn(fx, -2.12194440e-4f);
    x = __fsub_rn(x, tmp);
    x = __fsub_rn(x, z);

    float zz = __fmul_rn(x, x);

    float y = 1.9875691500e-4f;
    y = fmaf(y, x, 1.3981999507e-3f);
    y = fmaf(y, x, 8.3334519073e-3f);
    y = fmaf(y, x, 4.1665795894e-2f);
    y = fmaf(y, x, 1.6666665459e-1f);
    y = fmaf(y, x, 5.0000001201e-1f);
    y = fmaf(y, zz, x);
    y = __fadd_rn(y, 1.0f);

    int emm0 = (int)fx + 127;
    float pow2n = __int_as_float(emm0 << 23);
    return __fmul_rn(y, pow2n);
}

// One EXACT Newton step (bit-frozen op shapes from R9 — do not modify).
__device__ __forceinline__ float newton_step(float Te, float A_CONST, float A4,
                                             float B, float C, float C2, float D)
{
    float t   = __fadd_rn(Te, 273.16f);
    float t2  = __fmul_rn(t, t);
    float t4  = __fmul_rn(t2, t2);
    float t3  = __fmul_rn(t2, t);
    float m2  = __fmul_rn(C, __fmul_rn(Te, Te));
    float F   = __fsub_rn(fmaf(B, Te, fmaf(A_CONST, t4, -m2)), D);
    float c2t = __fmul_rn(C2, Te);
    float Fp  = __fadd_rn(fmaf(A4, t3, -c2t), B);
    return __fsub_rn(Te, __fdiv_rn(F, Fp));
}

__global__ void sntemp_kernel(
    const float* __restrict__ T_a,
    const float* __restrict__ swrad,
    const float* __restrict__ e_a,
    const float* __restrict__ E,
    const float* __restrict__ elev,
    const float* __restrict__ T_g,
    const float* __restrict__ sfr,
    const float* __restrict__ albedo,
    const float* __restrict__ shade_total,
    const float* __restrict__ cloud_fraction,
    const float* __restrict__ T_0,
    float* __restrict__ out,
    int n)
{
    int i  = blockIdx.x * blockDim.x + threadIdx.x;
    // No early return: clamp OOB lanes so warps stay full for __all_sync.
    int ii = (i < n) ? i : (n - 1);

    const float A_CONST = 5.4e-8f;
    const float A4      = (float)(4.0 * 5.4e-8);
    const float EV_STB  = (float)(0.9 * 5.670373e-8);
    const float C2495E6 = (float)(2495.0 * 1e6);

    float ta  = T_a[ii];
    float ea  = e_a[ii];
    float st  = shade_total[ii];
    float cf  = cloud_fraction[ii];
    float Ein = E[ii];

    // e_s = 6.108 * exp(17.26939*T_a / (237.3+T_a))
    float arg = __fdiv_rn(__fmul_rn(17.26939f, ta), __fadd_rn(237.3f, ta));
    float es  = __fmul_rn(6.108f, xla_vf32_exp(arg));

    // P = 1013.0 - 0.1055*elev   [plain]
    float P = __fsub_rn(1013.0f, __fmul_rn(0.1055f, elev[ii]));

    // masked denominator (from pre-rounded es) [plain]
    float denom  = __fsub_rn(es, ea);
    float denom1 = __fmul_rn(denom, (denom >= 0.0f) ? 1.0f : 0.0f);
    float denom2 = __fadd_rn(denom1, (denom1 == 0.0f) ? 0.01f : 0.0f);
    float Bc = __fdiv_rn(__fmul_rn(0.00061f, P), denom2);

    // Tk4 = (ta+273.16)^4
    float tk  = __fadd_rn(ta, 273.16f);
    float tk2 = __fmul_rn(tk, tk);
    float Tk4 = __fmul_rn(tk2, tk2);

    // H_a  [plain]
    float h1 = __fadd_rn(3.354939e-8f, __fmul_rn(2.74995e-9f, __fsqrt_rn(ea)));
    float h2 = __fsub_rn(1.0f, st);
    float h3 = __fadd_rn(1.0f, __fmul_rn(0.17f, __fmul_rn(cf, cf)));
    float Ha = __fmul_rn(__fmul_rn(__fmul_rn(h1, h2), h3), Tk4);

    // H_s  [plain]
    float Hs = __fmul_rn(__fmul_rn(__fsub_rn(1.0f, albedo[ii]), h2), swrad[ii]);

    // H_v  [plain]
    float Hv = __fmul_rn(__fmul_rn(EV_STB, sfr[ii]), Tk4);

    // B chain  [plain]
    float Em = __fmul_rn(1e6f, Ein);
    float b2 = __fadd_rn(2495.0f, __fmul_rn(2.36f, ta));
    float b4 = __fsub_rn(__fmul_rn(Bc, b2), 2.36f);
    float B  = __fadd_rn(__fmul_rn(Em, b4), 1.65f);

    // C  [plain]
    float C = __fmul_rn(__fmul_rn(Em, Bc), 2.36f);

    // D  [plain, reference association]
    float d3 = __fsub_rn(__fmul_rn(Bc, ta), 1.0f);
    float d4 = __fmul_rn(__fmul_rn(C2495E6, Ein), d3);
    float d5 = __fmul_rn(T_g[ii], 1.65f);
    float D  = __fadd_rn(__fadd_rn(__fadd_rn(__fadd_rn(Ha, Hs), Hv), d4), d5);

    float C2 = __fmul_rn(2.0f, C);

    // Newton: 50 exact iterations, as 25 double-steps with warp-uniform exit.
    float Te = ta;
    #pragma unroll 1
    for (int j = 0; j < 25; ++j) {
        float T1 = newton_step(Te, A_CONST, A4, B, C, C2, D);
        float T2 = newton_step(T1, A_CONST, A4, B, C, C2, D);
        bool conv = (T2 == Te);   // period <= 2 closure (fixed point or 2-cycle)
        Te = T2;                  // frozen lanes: T2 == Te, no-op
        if (__all_sync(0xffffffffu, conv)) break;
    }

    // Hi = F(T_0)  [plain — outside the loop]
    float t0   = T_0[ii];
    float u    = __fadd_rn(t0, 273.16f);
    float u2   = __fmul_rn(u, u);
    float u4   = __fmul_rn(u2, u2);
    float t0sq = __fmul_rn(t0, t0);
    float Hi   = __fsub_rn(
                   __fadd_rn(
                     __fsub_rn(__fmul_rn(A_CONST, u4), __fmul_rn(C, t0sq)),
                     __fmul_rn(B, t0)),
                   D);

    // K1 = F'(Te)  [plain — outside the loop]
    float v  = __fadd_rn(Te, 273.16f);
    float v2 = __fmul_rn(v, v);
    float v3 = __fmul_rn(v2, v);
    float K1 = __fadd_rn(
                 __fsub_rn(__fmul_rn(A4, v3), __fmul_rn(C2, Te)),
                 B);

    // K2  [plain]
    float delt = __fsub_rn(t0, Te);
    float den  = __fmul_rn(delt, delt);
    float den1 = __fadd_rn(den, (den <= 1e-10f) ? 1.0f : 0.0f);
    float K2   = __fdiv_rn(__fsub_rn(__fmul_rn(K1, delt), Hi), den1);
    if (fabsf(delt) < 1e-10f) K2 = 0.0f;

    if (i < n) {
        out[i]         = Te;
        out[n + i]     = K1;
        out[2 * n + i] = K2;
    }
}

extern "C" void kernel_launch(void* const* d_in, const int* in_sizes, int n_in,
                              void* d_out, int out_size) {
    // metadata order: T_a, swrad, e_a, E, elev, slope, top_width, up_inflow,
    // T_g, shade_fraction_riparian, albedo, shade_total, cloud_fraction, T_0
    const float* T_a    = (const float*)d_in[0];
    const float* swrad  = (const float*)d_in[1];
    const float* e_a    = (const float*)d_in[2];
    const float* E      = (const float*)d_in[3];
    const float* elev   = (const float*)d_in[4];
    const float* T_g    = (const float*)d_in[8];
    const float* sfr    = (const float*)d_in[9];
    const float* albedo = (const float*)d_in[10];
    const float* stot   = (const float*)d_in[11];
    const float* cf     = (const float*)d_in[12];
    const float* T_0    = (const float*)d_in[13];

    int n = in_sizes[0];
    float* out = (float*)d_out;

    int threads = 256;
    int blocks  = (n + threads - 1) / threads;
    sntemp_kernel<<<blocks, threads>>>(T_a, swrad, e_a, E, elev, T_g, sfr,
                                       albedo, stot, cf, T_0, out, n);
}

// round 11
// speedup vs baseline: 1.0616x; 1.0616x over previous
#include <cuda_runtime.h>
#include <math.h>

// Bit-exact replication of the JAX reference on XLA:CPU (validated R9, rel_err=0.0):
//   - outside fori_loop: all plain __f*_rn ops in reference association order
//   - inside fori_loop body: FMA-contracted F/Fp (separate XLA computation)
//   - exp = fused-Cephes GenerateVF32Exp
// R11 perf change: run EXACTLY 50 unconditional Newton iterations (reference
// semantics verbatim). R9/R10 profiling showed the terminal orbit wanders over
// several ulps (F jitter ~ ulp(D) maps to ~6e-8 rel on Te), so per-lane
// closure almost never happens and warps ran the full 50 anyway — the exit
// logic (2 FSETP + 2 BRA + BSSY/BSYNC + bookkeeping per iter) was pure
// overhead. Straight-line unrolled loop: ~20 instr/iter vs ~33.

__device__ __forceinline__ float xla_vf32_exp(float x)
{
    x = fminf(x, 88.3762626647950f);
    x = fmaxf(x, -88.3762626647949f);

    float fx = floorf(fmaf(x, 1.44269504088896341f, 0.5f));

    float tmp = __fmul_rn(fx, 0.693359375f);
    float z   = __fmul_rn(fx, -2.12194440e-4f);
    x = __fsub_rn(x, tmp);
    x = __fsub_rn(x, z);

    float zz = __fmul_rn(x, x);

    float y = 1.9875691500e-4f;
    y = fmaf(y, x, 1.3981999507e-3f);
    y = fmaf(y, x, 8.3334519073e-3f);
    y = fmaf(y, x, 4.1665795894e-2f);
    y = fmaf(y, x, 1.6666665459e-1f);
    y = fmaf(y, x, 5.0000001201e-1f);
    y = fmaf(y, zz, x);
    y = __fadd_rn(y, 1.0f);

    int emm0 = (int)fx + 127;
    float pow2n = __int_as_float(emm0 << 23);
    return __fmul_rn(y, pow2n);
}

__global__ void sntemp_kernel(
    const float* __restrict__ T_a,
    const float* __restrict__ swrad,
    const float* __restrict__ e_a,
    const float* __restrict__ E,
    const float* __restrict__ elev,
    const float* __restrict__ T_g,
    const float* __restrict__ sfr,
    const float* __restrict__ albedo,
    const float* __restrict__ shade_total,
    const float* __restrict__ cloud_fraction,
    const float* __restrict__ T_0,
    float* __restrict__ out,
    int n)
{
    int i = blockIdx.x * blockDim.x + threadIdx.x;
    if (i >= n) return;

    const float A_CONST = 5.4e-8f;
    const float A4      = (float)(4.0 * 5.4e-8);
    const float EV_STB  = (float)(0.9 * 5.670373e-8);
    const float C2495E6 = (float)(2495.0 * 1e6);

    float ta  = T_a[i];
    float ea  = e_a[i];
    float st  = shade_total[i];
    float cf  = cloud_fraction[i];
    float Ein = E[i];

    // e_s = 6.108 * exp(17.26939*T_a / (237.3+T_a))
    float arg = __fdiv_rn(__fmul_rn(17.26939f, ta), __fadd_rn(237.3f, ta));
    float es  = __fmul_rn(6.108f, xla_vf32_exp(arg));

    // P = 1013.0 - 0.1055*elev   [plain]
    float P = __fsub_rn(1013.0f, __fmul_rn(0.1055f, elev[i]));

    // masked denominator (from pre-rounded es) [plain]
    float denom  = __fsub_rn(es, ea);
    float denom1 = __fmul_rn(denom, (denom >= 0.0f) ? 1.0f : 0.0f);
    float denom2 = __fadd_rn(denom1, (denom1 == 0.0f) ? 0.01f : 0.0f);
    float Bc = __fdiv_rn(__fmul_rn(0.00061f, P), denom2);

    // Tk4 = (ta+273.16)^4
    float tk  = __fadd_rn(ta, 273.16f);
    float tk2 = __fmul_rn(tk, tk);
    float Tk4 = __fmul_rn(tk2, tk2);

    // H_a  [plain]
    float h1 = __fadd_rn(3.354939e-8f, __fmul_rn(2.74995e-9f, __fsqrt_rn(ea)));
    float h2 = __fsub_rn(1.0f, st);
    float h3 = __fadd_rn(1.0f, __fmul_rn(0.17f, __fmul_rn(cf, cf)));
    float Ha = __fmul_rn(__fmul_rn(__fmul_rn(h1, h2), h3), Tk4);

    // H_s  [plain]
    float Hs = __fmul_rn(__fmul_rn(__fsub_rn(1.0f, albedo[i]), h2), swrad[i]);

    // H_v  [plain]
    float Hv = __fmul_rn(__fmul_rn(EV_STB, sfr[i]), Tk4);

    // B chain  [plain]
    float Em = __fmul_rn(1e6f, Ein);
    float b2 = __fadd_rn(2495.0f, __fmul_rn(2.36f, ta));
    float b4 = __fsub_rn(__fmul_rn(Bc, b2), 2.36f);
    float B  = __fadd_rn(__fmul_rn(Em, b4), 1.65f);

    // C  [plain]
    float C = __fmul_rn(__fmul_rn(Em, Bc), 2.36f);

    // D  [plain, reference association]
    float d3 = __fsub_rn(__fmul_rn(Bc, ta), 1.0f);
    float d4 = __fmul_rn(__fmul_rn(C2495E6, Ein), d3);
    float d5 = __fmul_rn(T_g[i], 1.65f);
    float D  = __fadd_rn(__fadd_rn(__fadd_rn(__fadd_rn(Ha, Hs), Hv), d4), d5);

    float C2 = __fmul_rn(2.0f, C);

    // Newton: EXACTLY 50 unconditional iterations (reference semantics).
    // Loop body: FMA-contracted F/Fp (bit-frozen shapes — do not modify).
    float Te = ta;
    #pragma unroll 10
    for (int j = 0; j < 50; ++j) {
        float t   = __fadd_rn(Te, 273.16f);
        float t2  = __fmul_rn(t, t);
        float t4  = __fmul_rn(t2, t2);
        float t3  = __fmul_rn(t2, t);
        float m2  = __fmul_rn(C, __fmul_rn(Te, Te));
        float F   = __fsub_rn(fmaf(B, Te, fmaf(A_CONST, t4, -m2)), D);
        float c2t = __fmul_rn(C2, Te);
        float Fp  = __fadd_rn(fmaf(A4, t3, -c2t), B);
        Te = __fsub_rn(Te, __fdiv_rn(F, Fp));
    }

    // Hi = F(T_0)  [plain — outside the loop]
    float t0   = T_0[i];
    float u    = __fadd_rn(t0, 273.16f);
    float u2   = __fmul_rn(u, u);
    float u4   = __fmul_rn(u2, u2);
    float t0sq = __fmul_rn(t0, t0);
    float Hi   = __fsub_rn(
                   __fadd_rn(
                     __fsub_rn(__fmul_rn(A_CONST, u4), __fmul_rn(C, t0sq)),
                     __fmul_rn(B, t0)),
                   D);

    // K1 = F'(Te)  [plain — outside the loop]
    float v  = __fadd_rn(Te, 273.16f);
    float v2 = __fmul_rn(v, v);
    float v3 = __fmul_rn(v2, v);
    float K1 = __fadd_rn(
                 __fsub_rn(__fmul_rn(A4, v3), __fmul_rn(C2, Te)),
                 B);

    // K2  [plain]
    float delt = __fsub_rn(t0, Te);
    float den  = __fmul_rn(delt, delt);
    float den1 = __fadd_rn(den, (den <= 1e-10f) ? 1.0f : 0.0f);
    float K2   = __fdiv_rn(__fsub_rn(__fmul_rn(K1, delt), Hi), den1);
    if (fabsf(delt) < 1e-10f) K2 = 0.0f;

    out[i]         = Te;
    out[n + i]     = K1;
    out[2 * n + i] = K2;
}

extern "C" void kernel_launch(void* const* d_in, const int* in_sizes, int n_in,
                              void* d_out, int out_size) {
    // metadata order: T_a, swrad, e_a, E, elev, slope, top_width, up_inflow,
    // T_g, shade_fraction_riparian, albedo, shade_total, cloud_fraction, T_0
    const float* T_a    = (const float*)d_in[0];
    const float* swrad  = (const float*)d_in[1];
    const float* e_a    = (const float*)d_in[2];
    const float* E      = (const float*)d_in[3];
    const float* elev   = (const float*)d_in[4];
    const float* T_g    = (const float*)d_in[8];
    const float* sfr    = (const float*)d_in[9];
    const float* albedo = (const float*)d_in[10];
    const float* stot   = (const float*)d_in[11];
    const float* cf     = (const float*)d_in[12];
    const float* T_0    = (const float*)d_in[13];

    int n = in_sizes[0];
    float* out = (float*)d_out;

    int threads = 256;
    int blocks  = (n + threads - 1) / threads;
    sntemp_kernel<<<blocks, threads>>>(T_a, swrad, e_a, E, elev, T_g, sfr,
                                       albedo, stot, cf, T_0, out, n);
}

// round 12
// speedup vs baseline: 1.7714x; 1.6686x over previous
#include <cuda_runtime.h>
#include <math.h>

// Bit-exact replication of the JAX reference on XLA:CPU (validated R9, rel_err=0.0):
//   - outside fori_loop: all plain __f*_rn ops in reference association order
//   - inside fori_loop body: FMA-contracted F/Fp (separate XLA computation)
//   - exp = fused-Cephes GenerateVF32Exp
// R12 perf change (FP stream untouched): R9's per-lane early exit with minimal
// overhead. Iterations run in pairs; closure checks:
//   odd position :  T1 == Te            (fixed point; s50 = Te, no assign)
//   even position: (T2 == T1 || T2 == Te)  (fixed point at T1, or 2-cycle;
//                                           s50 = T2 in both, Te = T2)
// A 2-cycle first closing at an odd step is caught at the next even step via
// T2 == Te with the correct iteration-50 parity automatically (50 is even), so
// no prev register and no runtime parity logic. Lanes with no closure run all
// 25 pairs = exactly 50 exact steps. No warp votes (__all_sync costs ~23cyc on
// sm_103a — R10 lesson); per-lane predicated break only.

__device__ __forceinline__ float xla_vf32_exp(float x)
{
    x = fminf(x, 88.3762626647950f);
    x = fmaxf(x, -88.3762626647949f);

    float fx = floorf(fmaf(x, 1.44269504088896341f, 0.5f));

    float tmp = __fmul_rn(fx, 0.693359375f);
    float z   = __fmul_rn(fx, -2.12194440e-4f);
    x = __fsub_rn(x, tmp);
    x = __fsub_rn(x, z);

    float zz = __fmul_rn(x, x);

    float y = 1.9875691500e-4f;
    y = fmaf(y, x, 1.3981999507e-3f);
    y = fmaf(y, x, 8.3334519073e-3f);
    y = fmaf(y, x, 4.1665795894e-2f);
    y = fmaf(y, x, 1.6666665459e-1f);
    y = fmaf(y, x, 5.0000001201e-1f);
    y = fmaf(y, zz, x);
    y = __fadd_rn(y, 1.0f);

    int emm0 = (int)fx + 127;
    float pow2n = __int_as_float(emm0 << 23);
    return __fmul_rn(y, pow2n);
}

// One EXACT Newton step (bit-frozen op shapes from R9 — do not modify).
__device__ __forceinline__ float newton_step(float Te, float A_CONST, float A4,
                                             float B, float C, float C2, float D)
{
    float t   = __fadd_rn(Te, 273.16f);
    float t2  = __fmul_rn(t, t);
    float t4  = __fmul_rn(t2, t2);
    float t3  = __fmul_rn(t2, t);
    float m2  = __fmul_rn(C, __fmul_rn(Te, Te));
    float F   = __fsub_rn(fmaf(B, Te, fmaf(A_CONST, t4, -m2)), D);
    float c2t = __fmul_rn(C2, Te);
    float Fp  = __fadd_rn(fmaf(A4, t3, -c2t), B);
    return __fsub_rn(Te, __fdiv_rn(F, Fp));
}

__global__ void sntemp_kernel(
    const float* __restrict__ T_a,
    const float* __restrict__ swrad,
    const float* __restrict__ e_a,
    const float* __restrict__ E,
    const float* __restrict__ elev,
    const float* __restrict__ T_g,
    const float* __restrict__ sfr,
    const float* __restrict__ albedo,
    const float* __restrict__ shade_total,
    const float* __restrict__ cloud_fraction,
    const float* __restrict__ T_0,
    float* __restrict__ out,
    int n)
{
    int i = blockIdx.x * blockDim.x + threadIdx.x;
    if (i >= n) return;

    const float A_CONST = 5.4e-8f;
    const float A4      = (float)(4.0 * 5.4e-8);
    const float EV_STB  = (float)(0.9 * 5.670373e-8);
    const float C2495E6 = (float)(2495.0 * 1e6);

    float ta  = T_a[i];
    float ea  = e_a[i];
    float st  = shade_total[i];
    float cf  = cloud_fraction[i];
    float Ein = E[i];

    // e_s = 6.108 * exp(17.26939*T_a / (237.3+T_a))
    float arg = __fdiv_rn(__fmul_rn(17.26939f, ta), __fadd_rn(237.3f, ta));
    float es  = __fmul_rn(6.108f, xla_vf32_exp(arg));

    // P = 1013.0 - 0.1055*elev   [plain]
    float P = __fsub_rn(1013.0f, __fmul_rn(0.1055f, elev[i]));

    // masked denominator (from pre-rounded es) [plain]
    float denom  = __fsub_rn(es, ea);
    float denom1 = __fmul_rn(denom, (denom >= 0.0f) ? 1.0f : 0.0f);
    float denom2 = __fadd_rn(denom1, (denom1 == 0.0f) ? 0.01f : 0.0f);
    float Bc = __fdiv_rn(__fmul_rn(0.00061f, P), denom2);

    // Tk4 = (ta+273.16)^4
    float tk  = __fadd_rn(ta, 273.16f);
    float tk2 = __fmul_rn(tk, tk);
    float Tk4 = __fmul_rn(tk2, tk2);

    // H_a  [plain]
    float h1 = __fadd_rn(3.354939e-8f, __fmul_rn(2.74995e-9f, __fsqrt_rn(ea)));
    float h2 = __fsub_rn(1.0f, st);
    float h3 = __fadd_rn(1.0f, __fmul_rn(0.17f, __fmul_rn(cf, cf)));
    float Ha = __fmul_rn(__fmul_rn(__fmul_rn(h1, h2), h3), Tk4);

    // H_s  [plain]
    float Hs = __fmul_rn(__fmul_rn(__fsub_rn(1.0f, albedo[i]), h2), swrad[i]);

    // H_v  [plain]
    float Hv = __fmul_rn(__fmul_rn(EV_STB, sfr[i]), Tk4);

    // B chain  [plain]
    float Em = __fmul_rn(1e6f, Ein);
    float b2 = __fadd_rn(2495.0f, __fmul_rn(2.36f, ta));
    float b4 = __fsub_rn(__fmul_rn(Bc, b2), 2.36f);
    float B  = __fadd_rn(__fmul_rn(Em, b4), 1.65f);

    // C  [plain]
    float C = __fmul_rn(__fmul_rn(Em, Bc), 2.36f);

    // D  [plain, reference association]
    float d3 = __fsub_rn(__fmul_rn(Bc, ta), 1.0f);
    float d4 = __fmul_rn(__fmul_rn(C2495E6, Ein), d3);
    float d5 = __fmul_rn(T_g[i], 1.65f);
    float D  = __fadd_rn(__fadd_rn(__fadd_rn(__fadd_rn(Ha, Hs), Hv), d4), d5);

    float C2 = __fmul_rn(2.0f, C);

    // Newton: 50 exact iterations as 25 pairs with cheap per-lane closure exit.
    float Te = ta;
    #pragma unroll 1
    for (int j = 0; j < 25; ++j) {
        float T1 = newton_step(Te, A_CONST, A4, B, C, C2, D);   // step 2j+1 (odd)
        if (T1 == Te) break;                    // fixed point: s50 = Te (== T1)
        float T2 = newton_step(T1, A_CONST, A4, B, C, C2, D);   // step 2j+2 (even)
        if (T2 == T1 || T2 == Te) { Te = T2; break; }
        // T2==T1: fixed point at T1 -> s50 = T2.
        // T2==Te: 2-cycle closing at even step -> s50 = s_even = T2 (== Te).
        Te = T2;
    }

    // Hi = F(T_0)  [plain — outside the loop]
    float t0   = T_0[i];
    float u    = __fadd_rn(t0, 273.16f);
    float u2   = __fmul_rn(u, u);
    float u4   = __fmul_rn(u2, u2);
    float t0sq = __fmul_rn(t0, t0);
    float Hi   = __fsub_rn(
                   __fadd_rn(
                     __fsub_rn(__fmul_rn(A_CONST, u4), __fmul_rn(C, t0sq)),
                     __fmul_rn(B, t0)),
                   D);

    // K1 = F'(Te)  [plain — outside the loop]
    float v  = __fadd_rn(Te, 273.16f);
    float v2 = __fmul_rn(v, v);
    float v3 = __fmul_rn(v2, v);
    float K1 = __fadd_rn(
                 __fsub_rn(__fmul_rn(A4, v3), __fmul_rn(C2, Te)),
                 B);

    // K2  [plain]
    float delt = __fsub_rn(t0, Te);
    float den  = __fmul_rn(delt, delt);
    float den1 = __fadd_rn(den, (den <= 1e-10f) ? 1.0f : 0.0f);
    float K2   = __fdiv_rn(__fsub_rn(__fmul_rn(K1, delt), Hi), den1);
    if (fabsf(delt) < 1e-10f) K2 = 0.0f;

    out[i]         = Te;
    out[n + i]     = K1;
    out[2 * n + i] = K2;
}

extern "C" void kernel_launch(void* const* d_in, const int* in_sizes, int n_in,
                              void* d_out, int out_size) {
    // metadata order: T_a, swrad, e_a, E, elev, slope, top_width, up_inflow,
    // T_g, shade_fraction_riparian, albedo, shade_total, cloud_fraction, T_0
    const float* T_a    = (const float*)d_in[0];
    const float* swrad  = (const float*)d_in[1];
    const float* e_a    = (const float*)d_in[2];
    const float* E      = (const float*)d_in[3];
    const float* elev   = (const float*)d_in[4];
    const float* T_g    = (const float*)d_in[8];
    const float* sfr    = (const float*)d_in[9];
    const float* albedo = (const float*)d_in[10];
    const float* stot   = (const float*)d_in[11];
    const float* cf     = (const float*)d_in[12];
    const float* T_0    = (const float*)d_in[13];

    int n = in_sizes[0];
    float* out = (float*)d_out;

    int threads = 256;
    int blocks  = (n + threads - 1) / threads;
    sntemp_kernel<<<blocks, threads>>>(T_a, swrad, e_a, E, elev, T_g, sfr,
                                       albedo, stot, cf, T_0, out, n);
}

// round 13
// speedup vs baseline: 1.8127x; 1.0233x over previous
#include <cuda_runtime.h>
#include <math.h>

// Bit-exact replication of the JAX reference on XLA:CPU (validated R9/R12, rel_err=0.0):
//   - outside fori_loop: all plain __f*_rn ops in reference association order
//   - inside fori_loop body: FMA-contracted F/Fp (separate XLA computation)
//   - exp = fused-Cephes GenerateVF32Exp
// R13 perf change (FP stream untouched):
//   - single combined closure check per PAIR of exact steps:
//       (T2==T1): fixed point (incl. one reached at the odd step — the extra
//                 step is numerically idempotent), s50 = T2
//       (T2==Te): 2-cycle at even parity, s50 = T2 (50 is even)
//   - 25 pairs FULLY UNROLLED: no loop counter, forward-branch exits only.
//   Lanes with no closure run all 25 pairs = exactly 50 frozen-shape steps.

__device__ __forceinline__ float xla_vf32_exp(float x)
{
    x = fminf(x, 88.3762626647950f);
    x = fmaxf(x, -88.3762626647949f);

    float fx = floorf(fmaf(x, 1.44269504088896341f, 0.5f));

    float tmp = __fmul_rn(fx, 0.693359375f);
    float z   = __fmul_rn(fx, -2.12194440e-4f);
    x = __fsub_rn(x, tmp);
    x = __fsub_rn(x, z);

    float zz = __fmul_rn(x, x);

    float y = 1.9875691500e-4f;
    y = fmaf(y, x, 1.3981999507e-3f);
    y = fmaf(y, x, 8.3334519073e-3f);
    y = fmaf(y, x, 4.1665795894e-2f);
    y = fmaf(y, x, 1.6666665459e-1f);
    y = fmaf(y, x, 5.0000001201e-1f);
    y = fmaf(y, zz, x);
    y = __fadd_rn(y, 1.0f);

    int emm0 = (int)fx + 127;
    float pow2n = __int_as_float(emm0 << 23);
    return __fmul_rn(y, pow2n);
}

// One EXACT Newton step (bit-frozen op shapes from R9 — do not modify).
__device__ __forceinline__ float newton_step(float Te, float A_CONST, float A4,
                                             float B, float C, float C2, float D)
{
    float t   = __fadd_rn(Te, 273.16f);
    float t2  = __fmul_rn(t, t);
    float t4  = __fmul_rn(t2, t2);
    float t3  = __fmul_rn(t2, t);
    float m2  = __fmul_rn(C, __fmul_rn(Te, Te));
    float F   = __fsub_rn(fmaf(B, Te, fmaf(A_CONST, t4, -m2)), D);
    float c2t = __fmul_rn(C2, Te);
    float Fp  = __fadd_rn(fmaf(A4, t3, -c2t), B);
    return __fsub_rn(Te, __fdiv_rn(F, Fp));
}

__global__ void sntemp_kernel(
    const float* __restrict__ T_a,
    const float* __restrict__ swrad,
    const float* __restrict__ e_a,
    const float* __restrict__ E,
    const float* __restrict__ elev,
    const float* __restrict__ T_g,
    const float* __restrict__ sfr,
    const float* __restrict__ albedo,
    const float* __restrict__ shade_total,
    const float* __restrict__ cloud_fraction,
    const float* __restrict__ T_0,
    float* __restrict__ out,
    int n)
{
    int i = blockIdx.x * blockDim.x + threadIdx.x;
    if (i >= n) return;

    const float A_CONST = 5.4e-8f;
    const float A4      = (float)(4.0 * 5.4e-8);
    const float EV_STB  = (float)(0.9 * 5.670373e-8);
    const float C2495E6 = (float)(2495.0 * 1e6);

    float ta  = T_a[i];
    float ea  = e_a[i];
    float st  = shade_total[i];
    float cf  = cloud_fraction[i];
    float Ein = E[i];

    // e_s = 6.108 * exp(17.26939*T_a / (237.3+T_a))
    float arg = __fdiv_rn(__fmul_rn(17.26939f, ta), __fadd_rn(237.3f, ta));
    float es  = __fmul_rn(6.108f, xla_vf32_exp(arg));

    // P = 1013.0 - 0.1055*elev   [plain]
    float P = __fsub_rn(1013.0f, __fmul_rn(0.1055f, elev[i]));

    // masked denominator (from pre-rounded es) [plain]
    float denom  = __fsub_rn(es, ea);
    float denom1 = __fmul_rn(denom, (denom >= 0.0f) ? 1.0f : 0.0f);
    float denom2 = __fadd_rn(denom1, (denom1 == 0.0f) ? 0.01f : 0.0f);
    float Bc = __fdiv_rn(__fmul_rn(0.00061f, P), denom2);

    // Tk4 = (ta+273.16)^4
    float tk  = __fadd_rn(ta, 273.16f);
    float tk2 = __fmul_rn(tk, tk);
    float Tk4 = __fmul_rn(tk2, tk2);

    // H_a  [plain]
    float h1 = __fadd_rn(3.354939e-8f, __fmul_rn(2.74995e-9f, __fsqrt_rn(ea)));
    float h2 = __fsub_rn(1.0f, st);
    float h3 = __fadd_rn(1.0f, __fmul_rn(0.17f, __fmul_rn(cf, cf)));
    float Ha = __fmul_rn(__fmul_rn(__fmul_rn(h1, h2), h3), Tk4);

    // H_s  [plain]
    float Hs = __fmul_rn(__fmul_rn(__fsub_rn(1.0f, albedo[i]), h2), swrad[i]);

    // H_v  [plain]
    float Hv = __fmul_rn(__fmul_rn(EV_STB, sfr[i]), Tk4);

    // B chain  [plain]
    float Em = __fmul_rn(1e6f, Ein);
    float b2 = __fadd_rn(2495.0f, __fmul_rn(2.36f, ta));
    float b4 = __fsub_rn(__fmul_rn(Bc, b2), 2.36f);
    float B  = __fadd_rn(__fmul_rn(Em, b4), 1.65f);

    // C  [plain]
    float C = __fmul_rn(__fmul_rn(Em, Bc), 2.36f);

    // D  [plain, reference association]
    float d3 = __fsub_rn(__fmul_rn(Bc, ta), 1.0f);
    float d4 = __fmul_rn(__fmul_rn(C2495E6, Ein), d3);
    float d5 = __fmul_rn(T_g[i], 1.65f);
    float D  = __fadd_rn(__fadd_rn(__fadd_rn(__fadd_rn(Ha, Hs), Hv), d4), d5);

    float C2 = __fmul_rn(2.0f, C);

    // Newton: 50 exact iterations as 25 FULLY-UNROLLED pairs, one combined
    // per-lane closure check per pair.
    float Te = ta;
    #pragma unroll
    for (int j = 0; j < 25; ++j) {
        float T1 = newton_step(Te, A_CONST, A4, B, C, C2, D);   // step 2j+1
        float T2 = newton_step(T1, A_CONST, A4, B, C, C2, D);   // step 2j+2
        bool done = (T2 == T1) || (T2 == Te);
        Te = T2;
        if (done) break;
    }

    // Hi = F(T_0)  [plain — outside the loop]
    float t0   = T_0[i];
    float u    = __fadd_rn(t0, 273.16f);
    float u2   = __fmul_rn(u, u);
    float u4   = __fmul_rn(u2, u2);
    float t0sq = __fmul_rn(t0, t0);
    float Hi   = __fsub_rn(
                   __fadd_rn(
                     __fsub_rn(__fmul_rn(A_CONST, u4), __fmul_rn(C, t0sq)),
                     __fmul_rn(B, t0)),
                   D);

    // K1 = F'(Te)  [plain — outside the loop]
    float v  = __fadd_rn(Te, 273.16f);
    float v2 = __fmul_rn(v, v);
    float v3 = __fmul_rn(v2, v);
    float K1 = __fadd_rn(
                 __fsub_rn(__fmul_rn(A4, v3), __fmul_rn(C2, Te)),
                 B);

    // K2  [plain]
    float delt = __fsub_rn(t0, Te);
    float den  = __fmul_rn(delt, delt);
    float den1 = __fadd_rn(den, (den <= 1e-10f) ? 1.0f : 0.0f);
    float K2   = __fdiv_rn(__fsub_rn(__fmul_rn(K1, delt), Hi), den1);
    if (fabsf(delt) < 1e-10f) K2 = 0.0f;

    out[i]         = Te;
    out[n + i]     = K1;
    out[2 * n + i] = K2;
}

extern "C" void kernel_launch(void* const* d_in, const int* in_sizes, int n_in,
                              void* d_out, int out_size) {
    // metadata order: T_a, swrad, e_a, E, elev, slope, top_width, up_inflow,
    // T_g, shade_fraction_riparian, albedo, shade_total, cloud_fraction, T_0
    const float* T_a    = (const float*)d_in[0];
    const float* swrad  = (const float*)d_in[1];
    const float* e_a    = (const float*)d_in[2];
    const float* E      = (const float*)d_in[3];
    const float* elev   = (const float*)d_in[4];
    const float* T_g    = (const float*)d_in[8];
    const float* sfr    = (const float*)d_in[9];
    const float* albedo = (const float*)d_in[10];
    const float* stot   = (const float*)d_in[11];
    const float* cf     = (const float*)d_in[12];
    const float* T_0    = (const float*)d_in[13];

    int n = in_sizes[0];
    float* out = (float*)d_out;

    int threads = 256;
    int blocks  = (n + threads - 1) / threads;
    sntemp_kernel<<<blocks, threads>>>(T_a, swrad, e_a, E, elev, T_g, sfr,
                                       albedo, stot, cf, T_0, out, n);
}